// round 11
// baseline (speedup 1.0000x reference)
#include <cuda_runtime.h>
#include <cstdint>

#define NB 2
#define NS 2048
#define ND 1024
#define NH 16
#define HD 64
#define NR 129   // 2*64+1 relative buckets

typedef unsigned long long u64;

__device__ __forceinline__ void fma2(u64& d, u64 a, u64 b) {
    asm("fma.rn.f32x2 %0, %1, %2, %0;" : "+l"(d) : "l"(a), "l"(b));
}
__device__ __forceinline__ void mul2(u64& d, u64 a) {
    asm("mul.rn.f32x2 %0, %0, %1;" : "+l"(d) : "l"(a));
}
__device__ __forceinline__ u64 dup2(float x) {
    u64 o; unsigned r = __float_as_uint(x);
    asm("mov.b64 %0, {%1, %1};" : "=l"(o) : "r"(r));
    return o;
}
__device__ __forceinline__ float2 unpack2(u64 v) {
    unsigned lo, hi;
    asm("mov.b64 {%0, %1}, %2;" : "=r"(lo), "=r"(hi) : "l"(v));
    return make_float2(__uint_as_float(lo), __uint_as_float(hi));
}
__device__ __forceinline__ void cpa16(uint32_t s, const void* g) {
    asm volatile("cp.async.cg.shared.global [%0], [%1], 16;" :: "r"(s), "l"(g));
}
__device__ __forceinline__ void cp_commit() {
    asm volatile("cp.async.commit_group;");
}
__device__ __forceinline__ void cp_wait0() {
    asm volatile("cp.async.wait_group 0;");
}
__device__ __forceinline__ void cp_wait1() {
    asm volatile("cp.async.wait_group 1;");
}
__device__ __forceinline__ uint32_t smem_u32(const void* p) {
    return (uint32_t)__cvta_generic_to_shared(p);
}

// scratch (allocation-free rule: device globals)
__device__ float g_q[(size_t)NB * NH * NS * HD];   // pre-scaled by 1/sqrt(d)
__device__ float g_k[(size_t)NB * NH * NS * HD];
__device__ float g_v[(size_t)NB * NH * NS * HD];
__device__ float g_qe[(size_t)NB * NH * NS * NR];  // q . emb_k[r], scale folded in

// ---------------------------------------------------------------------------
// Kernel 1: fused QKV projection. 128x128 tile, BK=16, double-buffered smem,
// one barrier per step, B staged via cp.async (2 chunks/thread), FFMA2.
// ---------------------------------------------------------------------------
#define QBK 16
__global__ __launch_bounds__(256) void qkv_kernel(
    const float* __restrict__ hid,
    const float* __restrict__ Wq, const float* __restrict__ bq,
    const float* __restrict__ Wk, const float* __restrict__ bk,
    const float* __restrict__ Wv, const float* __restrict__ bv)
{
    const int bz = blockIdx.z;
    const float* W    = (bz == 0) ? Wq : (bz == 1) ? Wk : Wv;
    const float* bias = (bz == 0) ? bq : (bz == 1) ? bk : bv;
    float* out        = (bz == 0) ? g_q : (bz == 1) ? g_k : g_v;
    const float sc    = (bz == 0) ? 0.125f : 1.0f;   // 1/sqrt(64)

    __shared__ __align__(16) float As[2][QBK][132];   // [k][m]
    __shared__ __align__(16) float Bs[2][QBK][132];   // [k][n]

    const int tid = threadIdx.x;
    const int tx = tid & 15, ty = tid >> 4;
    const int m0 = blockIdx.y * 128, n0 = blockIdx.x * 128;

    const int arow = tid >> 1;            // 0..127 (m)
    const int acol = (tid & 1) * 8;       // k offset 0 or 8
    const int brow = tid >> 4;            // 0..15 (k)
    const int bc8  = (tid & 15) * 8;      // n offset, 8 floats via 2 cpa16

    u64 acc2[8][4];
#pragma unroll
    for (int i = 0; i < 8; i++)
#pragma unroll
        for (int j = 0; j < 4; j++) acc2[i][j] = 0ULL;

    // ---- prologue: stage tile 0 into buffer 0 ----
    {
        float4 a0 = *(const float4*)&hid[(size_t)(m0 + arow) * ND + acol];
        float4 a1 = *(const float4*)&hid[(size_t)(m0 + arow) * ND + acol + 4];
        As[0][acol + 0][arow] = a0.x; As[0][acol + 1][arow] = a0.y;
        As[0][acol + 2][arow] = a0.z; As[0][acol + 3][arow] = a0.w;
        As[0][acol + 4][arow] = a1.x; As[0][acol + 5][arow] = a1.y;
        As[0][acol + 6][arow] = a1.z; As[0][acol + 7][arow] = a1.w;
        cpa16(smem_u32(&Bs[0][brow][bc8]),     &W[(size_t)brow * ND + n0 + bc8]);
        cpa16(smem_u32(&Bs[0][brow][bc8 + 4]), &W[(size_t)brow * ND + n0 + bc8 + 4]);
        cp_commit();
        cp_wait0();
    }
    __syncthreads();

    int buf = 0;
    for (int k0 = 0; k0 < ND; k0 += QBK) {
        const bool more = (k0 + QBK) < ND;
        float4 a_n0, a_n1;
        if (more) {
            a_n0 = *(const float4*)&hid[(size_t)(m0 + arow) * ND + k0 + QBK + acol];
            a_n1 = *(const float4*)&hid[(size_t)(m0 + arow) * ND + k0 + QBK + acol + 4];
            cpa16(smem_u32(&Bs[buf ^ 1][brow][bc8]),
                  &W[(size_t)(k0 + QBK + brow) * ND + n0 + bc8]);
            cpa16(smem_u32(&Bs[buf ^ 1][brow][bc8 + 4]),
                  &W[(size_t)(k0 + QBK + brow) * ND + n0 + bc8 + 4]);
            cp_commit();
        }
#pragma unroll
        for (int kk = 0; kk < QBK; kk++) {
            float4 a0 = *(const float4*)&As[buf][kk][ty * 8];
            float4 a1 = *(const float4*)&As[buf][kk][ty * 8 + 4];
            ulonglong2 bl0 = *(const ulonglong2*)&Bs[buf][kk][tx * 8];
            ulonglong2 bl1 = *(const ulonglong2*)&Bs[buf][kk][tx * 8 + 4];
            u64 bvp[4] = {bl0.x, bl0.y, bl1.x, bl1.y};
            float av[8] = {a0.x, a0.y, a0.z, a0.w, a1.x, a1.y, a1.z, a1.w};
#pragma unroll
            for (int i = 0; i < 8; i++) {
                u64 ad = dup2(av[i]);
#pragma unroll
                for (int j = 0; j < 4; j++) fma2(acc2[i][j], ad, bvp[j]);
            }
        }
        if (more) {
            int nb = buf ^ 1;
            As[nb][acol + 0][arow] = a_n0.x; As[nb][acol + 1][arow] = a_n0.y;
            As[nb][acol + 2][arow] = a_n0.z; As[nb][acol + 3][arow] = a_n0.w;
            As[nb][acol + 4][arow] = a_n1.x; As[nb][acol + 5][arow] = a_n1.y;
            As[nb][acol + 6][arow] = a_n1.z; As[nb][acol + 7][arow] = a_n1.w;
            cp_wait0();
        }
        __syncthreads();
        buf ^= 1;
    }

#pragma unroll
    for (int i = 0; i < 8; i++) {
        int m = m0 + ty * 8 + i;           // m = b*S + s
        int b = m >> 11, s = m & (NS - 1);
#pragma unroll
        for (int jj = 0; jj < 2; jj++) {
            int n = n0 + tx * 8 + jj * 4;  // n = h*64 + d
            int h = n >> 6, dd = n & 63;
            float2 p0 = unpack2(acc2[i][jj * 2 + 0]);
            float2 p1 = unpack2(acc2[i][jj * 2 + 1]);
            float4 o;
            o.x = (p0.x + bias[n + 0]) * sc;
            o.y = (p0.y + bias[n + 1]) * sc;
            o.z = (p1.x + bias[n + 2]) * sc;
            o.w = (p1.y + bias[n + 3]) * sc;
            *(float4*)&out[(((size_t)(b * NH + h) * NS) + s) * HD + dd] = o;
        }
    }
}

// ---------------------------------------------------------------------------
// Kernel 2: qe[g][r] = sum_d g_q[g][d] * emb_k[r][d]
// ---------------------------------------------------------------------------
__global__ __launch_bounds__(128) void qe_kernel(const float* __restrict__ emb_k)
{
    __shared__ float eks[NR * 65];
    __shared__ float qs[32 * 65];
    const int tid = threadIdx.x;
    const size_t g0 = (size_t)blockIdx.x * 32;

    for (int i = tid; i < NR * HD; i += 128) {
        int r = i >> 6, d = i & 63;
        eks[r * 65 + d] = emb_k[i];
    }
    for (int i = tid; i < 32 * HD; i += 128) {
        int ql = i >> 6, d = i & 63;
        qs[ql * 65 + d] = g_q[(g0 + ql) * HD + d];
    }
    __syncthreads();

    for (int i = tid; i < 32 * NR; i += 128) {
        int ql = i / NR, r = i - ql * NR;
        float s = 0.f;
#pragma unroll
        for (int d = 0; d < HD; d++) s += qs[ql * 65 + d] * eks[r * 65 + d];
        g_qe[(g0 + ql) * NR + r] = s;
    }
}

// ---------------------------------------------------------------------------
// Kernel 3: flash attention. 256 threads, 2q x 8d microtile, double-buffered
// K/V via cp.async groups, FFMA2 packed, pw in absolute exp units.
// ---------------------------------------------------------------------------
__global__ __launch_bounds__(256) void attn_kernel(
    const float* __restrict__ mask, const float* __restrict__ emb_v,
    float* __restrict__ out)
{
    extern __shared__ float sm[];
    float* Qs  = sm;                     // [64][68]
    float* Ks0 = Qs  + 64 * 68;
    float* Ks1 = Ks0 + 64 * 68;
    float* Vs0 = Ks1 + 64 * 68;
    float* Vs1 = Vs0 + 64 * 68;
    float* Pt  = Vs1 + 64 * 68;          // [key][q]
    float* pwt = Pt  + 64 * 68;          // [129][68]
    float* mk  = pwt + NR * 68;          // [64]

    const int tid = threadIdx.x;
    const int tx = tid & 7, ty = tid >> 3;          // ty in [0,32)
    const int qt = blockIdx.x, bh = blockIdx.y;
    const int b = bh >> 4, h = bh & 15;
    const size_t base = (size_t)bh * NS * HD;
    const int q0 = qt * 64;

    const int srow = tid >> 4;            // 0..15
    const int sc4  = (tid & 15) * 4;      // 16B chunk

    float* Ksb[2] = {Ks0, Ks1};
    float* Vsb[2] = {Vs0, Vs1};

    // ---- prologue: stage Q + K/V tile 0 (one group) ----
    for (int r16 = 0; r16 < 64; r16 += 16) {
        cpa16(smem_u32(&Qs[(r16 + srow) * 68 + sc4]),
              &g_q[base + (size_t)(q0 + r16 + srow) * HD + sc4]);
        cpa16(smem_u32(&Ks0[(r16 + srow) * 68 + sc4]),
              &g_k[base + (size_t)(r16 + srow) * HD + sc4]);
        cpa16(smem_u32(&Vs0[(r16 + srow) * 68 + sc4]),
              &g_v[base + (size_t)(r16 + srow) * HD + sc4]);
    }
    cp_commit();
    for (int i = tid; i < NR * 68; i += 256) pwt[i] = 0.f;

    float qe0[2], qe128[2];
    const size_t qeb = ((size_t)bh * NS + q0) * NR;
#pragma unroll
    for (int i = 0; i < 2; i++) {
        int q = ty * 2 + i;
        qe0[i]   = g_qe[qeb + (size_t)q * NR + 0];
        qe128[i] = g_qe[qeb + (size_t)q * NR + 128];
    }

    float m_i[2], l_i[2];
    u64 acc2[2][4];
#pragma unroll
    for (int i = 0; i < 2; i++) {
        m_i[i] = -1e30f; l_i[i] = 0.f;
#pragma unroll
        for (int j = 0; j < 4; j++) acc2[i][j] = 0ULL;
    }

    for (int kt = 0; kt < NS / 64; kt++) {
        const int k0 = kt * 64;
        const int buf = kt & 1;
        // prefetch next K/V tile into alternate buffer (freed at kt-1 end)
        if (kt + 1 < NS / 64) {
            const int k1 = k0 + 64;
            for (int r16 = 0; r16 < 64; r16 += 16) {
                cpa16(smem_u32(&Ksb[buf ^ 1][(r16 + srow) * 68 + sc4]),
                      &g_k[base + (size_t)(k1 + r16 + srow) * HD + sc4]);
                cpa16(smem_u32(&Vsb[buf ^ 1][(r16 + srow) * 68 + sc4]),
                      &g_v[base + (size_t)(k1 + r16 + srow) * HD + sc4]);
            }
            cp_commit();
            cp_wait1();    // current tile's group done; next stays in flight
        } else {
            cp_wait0();
        }
        if (tid < 64) mk[tid] = mask[b * NS + k0 + tid];
        __syncthreads();

        const float* Ks = Ksb[buf];
        const float* Vs = Vsb[buf];

        // ---- S = Q K^T  (FFMA2 packed along d) ----
        u64 s2[2][8];
#pragma unroll
        for (int i = 0; i < 2; i++)
#pragma unroll
            for (int j = 0; j < 8; j++) s2[i][j] = 0ULL;
#pragma unroll 4
        for (int c4 = 0; c4 < HD; c4 += 4) {
            ulonglong2 aq[2], bk[8];
#pragma unroll
            for (int i = 0; i < 2; i++)
                aq[i] = *(const ulonglong2*)&Qs[(ty * 2 + i) * 68 + c4];
#pragma unroll
            for (int j = 0; j < 8; j++)
                bk[j] = *(const ulonglong2*)&Ks[(tx + 8 * j) * 68 + c4];
#pragma unroll
            for (int i = 0; i < 2; i++)
#pragma unroll
                for (int j = 0; j < 8; j++) {
                    fma2(s2[i][j], aq[i].x, bk[j].x);
                    fma2(s2[i][j], aq[i].y, bk[j].y);
                }
        }
        float s[2][8];
#pragma unroll
        for (int i = 0; i < 2; i++)
#pragma unroll
            for (int j = 0; j < 8; j++) {
                float2 p = unpack2(s2[i][j]);
                s[i][j] = p.x + p.y;
            }

        // ---- relative bias + mask ----
        const int dt = qt - kt;
        if (dt >= 2) {
#pragma unroll
            for (int i = 0; i < 2; i++)
#pragma unroll
                for (int j = 0; j < 8; j++) s[i][j] += qe128[i] + mk[tx + 8 * j];
        } else if (dt <= -2) {
#pragma unroll
            for (int i = 0; i < 2; i++)
#pragma unroll
                for (int j = 0; j < 8; j++) s[i][j] += qe0[i] + mk[tx + 8 * j];
        } else {
#pragma unroll
            for (int i = 0; i < 2; i++) {
                int qg = q0 + ty * 2 + i;
                const float* qer = &g_qe[((size_t)bh * NS + qg) * NR];
#pragma unroll
                for (int j = 0; j < 8; j++) {
                    int kg = k0 + tx + 8 * j;
                    int rp = qg - kg;
                    rp = rp < -64 ? -64 : (rp > 64 ? 64 : rp);
                    s[i][j] += __ldg(&qer[rp + 64]) + mk[tx + 8 * j];
                }
            }
        }

        // ---- streaming softmax ----
        float c[2], rstile[2], em[2];
#pragma unroll
        for (int i = 0; i < 2; i++) {
            float rmax = s[i][0];
#pragma unroll
            for (int j = 1; j < 8; j++) rmax = fmaxf(rmax, s[i][j]);
#pragma unroll
            for (int o = 1; o < 8; o <<= 1)
                rmax = fmaxf(rmax, __shfl_xor_sync(0xffffffffu, rmax, o));
            float mn = fmaxf(m_i[i], rmax);
            c[i] = __expf(m_i[i] - mn);
            m_i[i] = mn;
            em[i] = __expf(mn);            // abs-scale for pw (scores bounded)
            float rs = 0.f;
#pragma unroll
            for (int j = 0; j < 8; j++) { s[i][j] = __expf(s[i][j] - mn); rs += s[i][j]; }
#pragma unroll
            for (int o = 1; o < 8; o <<= 1) rs += __shfl_xor_sync(0xffffffffu, rs, o);
            l_i[i] = l_i[i] * c[i] + rs;
            rstile[i] = rs;
            u64 cd = dup2(c[i]);
#pragma unroll
            for (int j = 0; j < 4; j++) mul2(acc2[i][j], cd);
        }

        // stage P transposed [key][q] (q-pairs as STS.64)
#pragma unroll
        for (int j = 0; j < 8; j++)
            *(float2*)&Pt[(tx + 8 * j) * 68 + ty * 2] = make_float2(s[0][j], s[1][j]);

        // ---- bucket-probability accumulation (ABSOLUTE exp units) ----
        if (dt >= 2) {
            if (tx == 0)
#pragma unroll
                for (int i = 0; i < 2; i++)
                    pwt[128 * 68 + ty * 2 + i] += rstile[i] * em[i];
        } else if (dt <= -2) {
            if (tx == 0)
#pragma unroll
                for (int i = 0; i < 2; i++)
                    pwt[0 * 68 + ty * 2 + i] += rstile[i] * em[i];
        } else if (dt == -1) {
#pragma unroll
            for (int i = 0; i < 2; i++) {
                int qg = q0 + ty * 2 + i;
                float csum = 0.f;
#pragma unroll
                for (int j = 0; j < 8; j++) {
                    int kg = k0 + tx + 8 * j;
                    int rp = qg - kg;
                    float ps = s[i][j] * em[i];
                    if (rp <= -64) csum += ps;
                    else pwt[(rp + 64) * 68 + ty * 2 + i] += ps;
                }
#pragma unroll
                for (int o = 1; o < 8; o <<= 1)
                    csum += __shfl_xor_sync(0xffffffffu, csum, o);
                if (tx == 0) pwt[0 * 68 + ty * 2 + i] += csum;
            }
        } else if (dt == 1) {
#pragma unroll
            for (int i = 0; i < 2; i++) {
                int qg = q0 + ty * 2 + i;
                float csum = 0.f;
#pragma unroll
                for (int j = 0; j < 8; j++) {
                    int kg = k0 + tx + 8 * j;
                    int rp = qg - kg;
                    float ps = s[i][j] * em[i];
                    if (rp >= 64) csum += ps;
                    else pwt[(rp + 64) * 68 + ty * 2 + i] += ps;
                }
#pragma unroll
                for (int o = 1; o < 8; o <<= 1)
                    csum += __shfl_xor_sync(0xffffffffu, csum, o);
                if (tx == 0) pwt[128 * 68 + ty * 2 + i] += csum;
            }
        } else {
#pragma unroll
            for (int i = 0; i < 2; i++) {
                int qg = q0 + ty * 2 + i;
#pragma unroll
                for (int j = 0; j < 8; j++) {
                    int kg = k0 + tx + 8 * j;
                    int rp = qg - kg;
                    pwt[(rp + 64) * 68 + ty * 2 + i] += s[i][j] * em[i];
                }
            }
        }
        __syncthreads();   // Pt visible to all before PV

        // ---- O += P V  (d-cols tx*4 and 32+tx*4: conflict-free) ----
#pragma unroll 4
        for (int k = 0; k < 64; k++) {
            float2 p2 = *(const float2*)&Pt[k * 68 + ty * 2];
            ulonglong2 v0 = *(const ulonglong2*)&Vs[k * 68 + tx * 4];
            ulonglong2 v1 = *(const ulonglong2*)&Vs[k * 68 + 32 + tx * 4];
            u64 vv[4] = {v0.x, v0.y, v1.x, v1.y};
            u64 pd[2] = {dup2(p2.x), dup2(p2.y)};
#pragma unroll
            for (int i = 0; i < 2; i++)
#pragma unroll
                for (int j = 0; j < 4; j++) fma2(acc2[i][j], pd[i], vv[j]);
        }
        __syncthreads();   // frees Pt/mk; K/V buf reused only at kt+2
    }

    // ---- epilogue: ctx_rel = pw @ emb_v ----
    float* evs = Qs;   // 129*64 = 8256 floats <= 8704 (Qs+Ks0)
    for (int i = tid; i < NR * HD; i += 256) evs[i] = emb_v[i];
    __syncthreads();

    u64 rel2[2][4];
#pragma unroll
    for (int i = 0; i < 2; i++)
#pragma unroll
        for (int j = 0; j < 4; j++) rel2[i][j] = 0ULL;
#pragma unroll 4
    for (int r = 0; r < NR; r++) {
        float2 p2 = *(const float2*)&pwt[r * 68 + ty * 2];
        ulonglong2 e0 = *(const ulonglong2*)&evs[r * HD + tx * 4];
        ulonglong2 e1 = *(const ulonglong2*)&evs[r * HD + 32 + tx * 4];
        u64 ev[4] = {e0.x, e0.y, e1.x, e1.y};
        u64 pd[2] = {dup2(p2.x), dup2(p2.y)};
#pragma unroll
        for (int i = 0; i < 2; i++)
#pragma unroll
            for (int j = 0; j < 4; j++) fma2(rel2[i][j], pd[i], ev[j]);
    }

#pragma unroll
    for (int i = 0; i < 2; i++) {
        int qg = q0 + ty * 2 + i;
        float inv = 1.0f / l_i[i];
        float emf = __expf(-m_i[i]);       // undo absolute scale on pw
        float* op = &out[((size_t)(b * NS + qg)) * ND + h * HD];
        float o[8];
#pragma unroll
        for (int j = 0; j < 4; j++) {
            float2 a = unpack2(acc2[i][j]);
            float2 rl = unpack2(rel2[i][j]);
            o[j * 2 + 0] = (a.x + rl.x * emf) * inv;
            o[j * 2 + 1] = (a.y + rl.y * emf) * inv;
        }
        *(float4*)&op[tx * 4]      = make_float4(o[0], o[1], o[2], o[3]);
        *(float4*)&op[32 + tx * 4] = make_float4(o[4], o[5], o[6], o[7]);
    }
}

// ---------------------------------------------------------------------------
extern "C" void kernel_launch(void* const* d_in, const int* in_sizes, int n_in,
                              void* d_out, int out_size)
{
    const float* hid   = (const float*)d_in[0];
    const float* mask  = (const float*)d_in[1];
    const float* Wq    = (const float*)d_in[2];
    const float* bq    = (const float*)d_in[3];
    const float* Wk    = (const float*)d_in[4];
    const float* bk    = (const float*)d_in[5];
    const float* Wv    = (const float*)d_in[6];
    const float* bv    = (const float*)d_in[7];
    const float* emb_k = (const float*)d_in[8];
    const float* emb_v = (const float*)d_in[9];
    float* out = (float*)d_out;

    dim3 g1(ND / 128, (NB * NS) / 128, 3);
    qkv_kernel<<<g1, 256>>>(hid, Wq, bq, Wk, bk, Wv, bv);

    qe_kernel<<<(NB * NH * NS) / 32, 128>>>(emb_k);

    size_t smem = (size_t)(6 * 64 * 68 + NR * 68 + 64) * sizeof(float);
    cudaFuncSetAttribute(attn_kernel, cudaFuncAttributeMaxDynamicSharedMemorySize,
                         (int)smem);
    attn_kernel<<<dim3(NS / 64, NB * NH), 256, smem>>>(mask, emb_v, out);
}

// round 12
// speedup vs baseline: 1.0597x; 1.0597x over previous
#include <cuda_runtime.h>
#include <cstdint>

#define NB 2
#define NS 2048
#define ND 1024
#define NH 16
#define HD 64
#define NR 129   // 2*64+1 relative buckets

typedef unsigned long long u64;

__device__ __forceinline__ void fma2(u64& d, u64 a, u64 b) {
    asm("fma.rn.f32x2 %0, %1, %2, %0;" : "+l"(d) : "l"(a), "l"(b));
}
__device__ __forceinline__ void mul2(u64& d, u64 a) {
    asm("mul.rn.f32x2 %0, %0, %1;" : "+l"(d) : "l"(a));
}
__device__ __forceinline__ u64 dup2(float x) {
    u64 o; unsigned r = __float_as_uint(x);
    asm("mov.b64 %0, {%1, %1};" : "=l"(o) : "r"(r));
    return o;
}
__device__ __forceinline__ float2 unpack2(u64 v) {
    unsigned lo, hi;
    asm("mov.b64 {%0, %1}, %2;" : "=r"(lo), "=r"(hi) : "l"(v));
    return make_float2(__uint_as_float(lo), __uint_as_float(hi));
}
__device__ __forceinline__ void cpa16(uint32_t s, const void* g) {
    asm volatile("cp.async.cg.shared.global [%0], [%1], 16;" :: "r"(s), "l"(g));
}
__device__ __forceinline__ void cp_commit() {
    asm volatile("cp.async.commit_group;");
}
__device__ __forceinline__ void cp_wait0() {
    asm volatile("cp.async.wait_group 0;");
}
__device__ __forceinline__ void cp_wait1() {
    asm volatile("cp.async.wait_group 1;");
}
__device__ __forceinline__ uint32_t smem_u32(const void* p) {
    return (uint32_t)__cvta_generic_to_shared(p);
}

// scratch (allocation-free rule: device globals)
__device__ float g_q[(size_t)NB * NH * NS * HD];   // pre-scaled by 1/sqrt(d)
__device__ float g_k[(size_t)NB * NH * NS * HD];
__device__ float g_v[(size_t)NB * NH * NS * HD];
__device__ float g_qe[(size_t)NB * NH * NS * NR];  // q . emb_k[r], scale folded in

// ---------------------------------------------------------------------------
// Kernel 1: fused QKV projection. 128x128 tile, BK=16, double-buffered smem,
// one barrier per step, B staged via cp.async (2 chunks/thread), FFMA2.
// ---------------------------------------------------------------------------
#define QBK 16
__global__ __launch_bounds__(256) void qkv_kernel(
    const float* __restrict__ hid,
    const float* __restrict__ Wq, const float* __restrict__ bq,
    const float* __restrict__ Wk, const float* __restrict__ bk,
    const float* __restrict__ Wv, const float* __restrict__ bv)
{
    const int bz = blockIdx.z;
    const float* W    = (bz == 0) ? Wq : (bz == 1) ? Wk : Wv;
    const float* bias = (bz == 0) ? bq : (bz == 1) ? bk : bv;
    float* out        = (bz == 0) ? g_q : (bz == 1) ? g_k : g_v;
    const float sc    = (bz == 0) ? 0.125f : 1.0f;   // 1/sqrt(64)

    __shared__ __align__(16) float As[2][QBK][132];   // [k][m]
    __shared__ __align__(16) float Bs[2][QBK][132];   // [k][n]

    const int tid = threadIdx.x;
    const int tx = tid & 15, ty = tid >> 4;
    const int m0 = blockIdx.y * 128, n0 = blockIdx.x * 128;

    const int arow = tid >> 1;            // 0..127 (m)
    const int acol = (tid & 1) * 8;       // k offset 0 or 8
    const int brow = tid >> 4;            // 0..15 (k)
    const int bc8  = (tid & 15) * 8;      // n offset, 8 floats via 2 cpa16

    u64 acc2[8][4];
#pragma unroll
    for (int i = 0; i < 8; i++)
#pragma unroll
        for (int j = 0; j < 4; j++) acc2[i][j] = 0ULL;

    // ---- prologue: stage tile 0 into buffer 0 ----
    {
        float4 a0 = *(const float4*)&hid[(size_t)(m0 + arow) * ND + acol];
        float4 a1 = *(const float4*)&hid[(size_t)(m0 + arow) * ND + acol + 4];
        As[0][acol + 0][arow] = a0.x; As[0][acol + 1][arow] = a0.y;
        As[0][acol + 2][arow] = a0.z; As[0][acol + 3][arow] = a0.w;
        As[0][acol + 4][arow] = a1.x; As[0][acol + 5][arow] = a1.y;
        As[0][acol + 6][arow] = a1.z; As[0][acol + 7][arow] = a1.w;
        cpa16(smem_u32(&Bs[0][brow][bc8]),     &W[(size_t)brow * ND + n0 + bc8]);
        cpa16(smem_u32(&Bs[0][brow][bc8 + 4]), &W[(size_t)brow * ND + n0 + bc8 + 4]);
        cp_commit();
        cp_wait0();
    }
    __syncthreads();

    int buf = 0;
    for (int k0 = 0; k0 < ND; k0 += QBK) {
        const bool more = (k0 + QBK) < ND;
        float4 a_n0, a_n1;
        if (more) {
            a_n0 = *(const float4*)&hid[(size_t)(m0 + arow) * ND + k0 + QBK + acol];
            a_n1 = *(const float4*)&hid[(size_t)(m0 + arow) * ND + k0 + QBK + acol + 4];
            cpa16(smem_u32(&Bs[buf ^ 1][brow][bc8]),
                  &W[(size_t)(k0 + QBK + brow) * ND + n0 + bc8]);
            cpa16(smem_u32(&Bs[buf ^ 1][brow][bc8 + 4]),
                  &W[(size_t)(k0 + QBK + brow) * ND + n0 + bc8 + 4]);
            cp_commit();
        }
#pragma unroll
        for (int kk = 0; kk < QBK; kk++) {
            float4 a0 = *(const float4*)&As[buf][kk][ty * 8];
            float4 a1 = *(const float4*)&As[buf][kk][ty * 8 + 4];
            ulonglong2 bl0 = *(const ulonglong2*)&Bs[buf][kk][tx * 8];
            ulonglong2 bl1 = *(const ulonglong2*)&Bs[buf][kk][tx * 8 + 4];
            u64 bvp[4] = {bl0.x, bl0.y, bl1.x, bl1.y};
            float av[8] = {a0.x, a0.y, a0.z, a0.w, a1.x, a1.y, a1.z, a1.w};
#pragma unroll
            for (int i = 0; i < 8; i++) {
                u64 ad = dup2(av[i]);
#pragma unroll
                for (int j = 0; j < 4; j++) fma2(acc2[i][j], ad, bvp[j]);
            }
        }
        if (more) {
            int nb = buf ^ 1;
            As[nb][acol + 0][arow] = a_n0.x; As[nb][acol + 1][arow] = a_n0.y;
            As[nb][acol + 2][arow] = a_n0.z; As[nb][acol + 3][arow] = a_n0.w;
            As[nb][acol + 4][arow] = a_n1.x; As[nb][acol + 5][arow] = a_n1.y;
            As[nb][acol + 6][arow] = a_n1.z; As[nb][acol + 7][arow] = a_n1.w;
            cp_wait0();
        }
        __syncthreads();
        buf ^= 1;
    }

#pragma unroll
    for (int i = 0; i < 8; i++) {
        int m = m0 + ty * 8 + i;           // m = b*S + s
        int b = m >> 11, s = m & (NS - 1);
#pragma unroll
        for (int jj = 0; jj < 2; jj++) {
            int n = n0 + tx * 8 + jj * 4;  // n = h*64 + d
            int h = n >> 6, dd = n & 63;
            float2 p0 = unpack2(acc2[i][jj * 2 + 0]);
            float2 p1 = unpack2(acc2[i][jj * 2 + 1]);
            float4 o;
            o.x = (p0.x + bias[n + 0]) * sc;
            o.y = (p0.y + bias[n + 1]) * sc;
            o.z = (p1.x + bias[n + 2]) * sc;
            o.w = (p1.y + bias[n + 3]) * sc;
            *(float4*)&out[(((size_t)(b * NH + h) * NS) + s) * HD + dd] = o;
        }
    }
}

// ---------------------------------------------------------------------------
// Kernel 2: qe[g][r] = sum_d g_q[g][d] * emb_k[r][d]
// ---------------------------------------------------------------------------
__global__ __launch_bounds__(128) void qe_kernel(const float* __restrict__ emb_k)
{
    __shared__ float eks[NR * 65];
    __shared__ float qs[32 * 65];
    const int tid = threadIdx.x;
    const size_t g0 = (size_t)blockIdx.x * 32;

    for (int i = tid; i < NR * HD; i += 128) {
        int r = i >> 6, d = i & 63;
        eks[r * 65 + d] = emb_k[i];
    }
    for (int i = tid; i < 32 * HD; i += 128) {
        int ql = i >> 6, d = i & 63;
        qs[ql * 65 + d] = g_q[(g0 + ql) * HD + d];
    }
    __syncthreads();

    for (int i = tid; i < 32 * NR; i += 128) {
        int ql = i / NR, r = i - ql * NR;
        float s = 0.f;
#pragma unroll
        for (int d = 0; d < HD; d++) s += qs[ql * 65 + d] * eks[r * 65 + d];
        g_qe[(g0 + ql) * NR + r] = s;
    }
}

// ---------------------------------------------------------------------------
// Kernel 3: flash attention. 128 threads, 4q x 8d microtile (R10 shape),
// double-buffered K/V via cp.async groups, FFMA2, pw in absolute exp units.
// ---------------------------------------------------------------------------
__global__ __launch_bounds__(128) void attn_kernel(
    const float* __restrict__ mask, const float* __restrict__ emb_v,
    float* __restrict__ out)
{
    extern __shared__ float sm[];
    float* Qs  = sm;                     // [64][68]
    float* Ks0 = Qs  + 64 * 68;
    float* Ks1 = Ks0 + 64 * 68;
    float* Vs0 = Ks1 + 64 * 68;
    float* Vs1 = Vs0 + 64 * 68;
    float* Pt  = Vs1 + 64 * 68;          // [key][q]
    float* pwt = Pt  + 64 * 68;          // [129][68]
    float* mk  = pwt + NR * 68;          // [64]

    const int tid = threadIdx.x;
    const int tx = tid & 7, ty = tid >> 3;          // ty in [0,16)
    const int qt = blockIdx.x, bh = blockIdx.y;
    const int b = bh >> 4, h = bh & 15;
    const size_t base = (size_t)bh * NS * HD;
    const int q0 = qt * 64;

    const int srow = tid >> 4;            // 0..7, staging rows
    const int sc4  = (tid & 15) * 4;      // 16B chunk

    float* Ksb[2] = {Ks0, Ks1};
    float* Vsb[2] = {Vs0, Vs1};

    // ---- prologue: stage Q + K/V tile 0 (one group) ----
    for (int r8 = 0; r8 < 64; r8 += 8) {
        cpa16(smem_u32(&Qs[(r8 + srow) * 68 + sc4]),
              &g_q[base + (size_t)(q0 + r8 + srow) * HD + sc4]);
        cpa16(smem_u32(&Ks0[(r8 + srow) * 68 + sc4]),
              &g_k[base + (size_t)(r8 + srow) * HD + sc4]);
        cpa16(smem_u32(&Vs0[(r8 + srow) * 68 + sc4]),
              &g_v[base + (size_t)(r8 + srow) * HD + sc4]);
    }
    cp_commit();
    for (int i = tid; i < NR * 68; i += 128) pwt[i] = 0.f;

    float qe0[4], qe128[4];
    const size_t qeb = ((size_t)bh * NS + q0) * NR;
#pragma unroll
    for (int i = 0; i < 4; i++) {
        int q = ty * 4 + i;
        qe0[i]   = g_qe[qeb + (size_t)q * NR + 0];
        qe128[i] = g_qe[qeb + (size_t)q * NR + 128];
    }

    float m_i[4], l_i[4];
    u64 acc2[4][4];
#pragma unroll
    for (int i = 0; i < 4; i++) {
        m_i[i] = -1e30f; l_i[i] = 0.f;
#pragma unroll
        for (int j = 0; j < 4; j++) acc2[i][j] = 0ULL;
    }

    for (int kt = 0; kt < NS / 64; kt++) {
        const int k0 = kt * 64;
        const int buf = kt & 1;
        // prefetch next K/V tile into alternate buffer (reads done: barrier
        // at end of tile kt-1 covers all consumers of buf^1)
        if (kt + 1 < NS / 64) {
            const int k1 = k0 + 64;
            for (int r8 = 0; r8 < 64; r8 += 8) {
                cpa16(smem_u32(&Ksb[buf ^ 1][(r8 + srow) * 68 + sc4]),
                      &g_k[base + (size_t)(k1 + r8 + srow) * HD + sc4]);
                cpa16(smem_u32(&Vsb[buf ^ 1][(r8 + srow) * 68 + sc4]),
                      &g_v[base + (size_t)(k1 + r8 + srow) * HD + sc4]);
            }
            cp_commit();
            cp_wait1();    // current tile's group complete; prefetch in flight
        } else {
            cp_wait0();
        }
        if (tid < 64) mk[tid] = mask[b * NS + k0 + tid];
        __syncthreads();

        const float* Ks = Ksb[buf];
        const float* Vs = Vsb[buf];

        // ---- S = Q K^T  (FFMA2 packed along d) ----
        u64 s2[4][8];
#pragma unroll
        for (int i = 0; i < 4; i++)
#pragma unroll
            for (int j = 0; j < 8; j++) s2[i][j] = 0ULL;
#pragma unroll 4
        for (int c4 = 0; c4 < HD; c4 += 4) {
            ulonglong2 aq[4], bk[8];
#pragma unroll
            for (int i = 0; i < 4; i++)
                aq[i] = *(const ulonglong2*)&Qs[(ty * 4 + i) * 68 + c4];
#pragma unroll
            for (int j = 0; j < 8; j++)
                bk[j] = *(const ulonglong2*)&Ks[(tx + 8 * j) * 68 + c4];
#pragma unroll
            for (int i = 0; i < 4; i++)
#pragma unroll
                for (int j = 0; j < 8; j++) {
                    fma2(s2[i][j], aq[i].x, bk[j].x);
                    fma2(s2[i][j], aq[i].y, bk[j].y);
                }
        }
        float s[4][8];
#pragma unroll
        for (int i = 0; i < 4; i++)
#pragma unroll
            for (int j = 0; j < 8; j++) {
                float2 p = unpack2(s2[i][j]);
                s[i][j] = p.x + p.y;
            }

        // ---- relative bias + mask ----
        const int dt = qt - kt;
        if (dt >= 2) {
#pragma unroll
            for (int i = 0; i < 4; i++)
#pragma unroll
                for (int j = 0; j < 8; j++) s[i][j] += qe128[i] + mk[tx + 8 * j];
        } else if (dt <= -2) {
#pragma unroll
            for (int i = 0; i < 4; i++)
#pragma unroll
                for (int j = 0; j < 8; j++) s[i][j] += qe0[i] + mk[tx + 8 * j];
        } else {
#pragma unroll
            for (int i = 0; i < 4; i++) {
                int qg = q0 + ty * 4 + i;
                const float* qer = &g_qe[((size_t)bh * NS + qg) * NR];
#pragma unroll
                for (int j = 0; j < 8; j++) {
                    int kg = k0 + tx + 8 * j;
                    int rp = qg - kg;
                    rp = rp < -64 ? -64 : (rp > 64 ? 64 : rp);
                    s[i][j] += __ldg(&qer[rp + 64]) + mk[tx + 8 * j];
                }
            }
        }

        // ---- streaming softmax ----
        float c[4], rstile[4], em[4];
#pragma unroll
        for (int i = 0; i < 4; i++) {
            float rmax = s[i][0];
#pragma unroll
            for (int j = 1; j < 8; j++) rmax = fmaxf(rmax, s[i][j]);
#pragma unroll
            for (int o = 1; o < 8; o <<= 1)
                rmax = fmaxf(rmax, __shfl_xor_sync(0xffffffffu, rmax, o));
            float mn = fmaxf(m_i[i], rmax);
            c[i] = __expf(m_i[i] - mn);
            m_i[i] = mn;
            em[i] = __expf(mn);            // abs-scale for pw (scores bounded)
            float rs = 0.f;
#pragma unroll
            for (int j = 0; j < 8; j++) { s[i][j] = __expf(s[i][j] - mn); rs += s[i][j]; }
#pragma unroll
            for (int o = 1; o < 8; o <<= 1) rs += __shfl_xor_sync(0xffffffffu, rs, o);
            l_i[i] = l_i[i] * c[i] + rs;
            rstile[i] = rs;
            u64 cd = dup2(c[i]);
#pragma unroll
            for (int j = 0; j < 4; j++) mul2(acc2[i][j], cd);
        }

        // stage P transposed [key][q]
#pragma unroll
        for (int i = 0; i < 4; i++)
#pragma unroll
            for (int j = 0; j < 8; j++)
                Pt[(tx + 8 * j) * 68 + ty * 4 + i] = s[i][j];

        // ---- bucket-probability accumulation (ABSOLUTE exp units) ----
        if (dt >= 2) {
            if (tx == 0)
#pragma unroll
                for (int i = 0; i < 4; i++)
                    pwt[128 * 68 + ty * 4 + i] += rstile[i] * em[i];
        } else if (dt <= -2) {
            if (tx == 0)
#pragma unroll
                for (int i = 0; i < 4; i++)
                    pwt[0 * 68 + ty * 4 + i] += rstile[i] * em[i];
        } else if (dt == -1) {
#pragma unroll
            for (int i = 0; i < 4; i++) {
                int qg = q0 + ty * 4 + i;
                float csum = 0.f;
#pragma unroll
                for (int j = 0; j < 8; j++) {
                    int kg = k0 + tx + 8 * j;
                    int rp = qg - kg;
                    float ps = s[i][j] * em[i];
                    if (rp <= -64) csum += ps;
                    else pwt[(rp + 64) * 68 + ty * 4 + i] += ps;
                }
#pragma unroll
                for (int o = 1; o < 8; o <<= 1)
                    csum += __shfl_xor_sync(0xffffffffu, csum, o);
                if (tx == 0) pwt[0 * 68 + ty * 4 + i] += csum;
            }
        } else if (dt == 1) {
#pragma unroll
            for (int i = 0; i < 4; i++) {
                int qg = q0 + ty * 4 + i;
                float csum = 0.f;
#pragma unroll
                for (int j = 0; j < 8; j++) {
                    int kg = k0 + tx + 8 * j;
                    int rp = qg - kg;
                    float ps = s[i][j] * em[i];
                    if (rp >= 64) csum += ps;
                    else pwt[(rp + 64) * 68 + ty * 4 + i] += ps;
                }
#pragma unroll
                for (int o = 1; o < 8; o <<= 1)
                    csum += __shfl_xor_sync(0xffffffffu, csum, o);
                if (tx == 0) pwt[128 * 68 + ty * 4 + i] += csum;
            }
        } else {
#pragma unroll
            for (int i = 0; i < 4; i++) {
                int qg = q0 + ty * 4 + i;
#pragma unroll
                for (int j = 0; j < 8; j++) {
                    int kg = k0 + tx + 8 * j;
                    int rp = qg - kg;
                    pwt[(rp + 64) * 68 + ty * 4 + i] += s[i][j] * em[i];
                }
            }
        }
        __syncthreads();   // Pt visible to all before PV

        // ---- O += P V  (d-cols tx*4 and 32+tx*4: conflict-free) ----
#pragma unroll 4
        for (int k = 0; k < 64; k++) {
            float4 p4 = *(const float4*)&Pt[k * 68 + ty * 4];
            ulonglong2 v0 = *(const ulonglong2*)&Vs[k * 68 + tx * 4];
            ulonglong2 v1 = *(const ulonglong2*)&Vs[k * 68 + 32 + tx * 4];
            u64 vv[4] = {v0.x, v0.y, v1.x, v1.y};
            u64 pd[4] = {dup2(p4.x), dup2(p4.y), dup2(p4.z), dup2(p4.w)};
#pragma unroll
            for (int i = 0; i < 4; i++)
#pragma unroll
                for (int j = 0; j < 4; j++) fma2(acc2[i][j], pd[i], vv[j]);
        }
        __syncthreads();   // frees Pt/mk; K/V buf reused only at kt+2
    }

    // ---- epilogue: ctx_rel = pw @ emb_v ----
    float* evs = Qs;   // 129*64 = 8256 floats <= 8704 (Qs+Ks0)
    for (int i = tid; i < NR * HD; i += 128) evs[i] = emb_v[i];
    __syncthreads();

    u64 rel2[4][4];
#pragma unroll
    for (int i = 0; i < 4; i++)
#pragma unroll
        for (int j = 0; j < 4; j++) rel2[i][j] = 0ULL;
#pragma unroll 4
    for (int r = 0; r < NR; r++) {
        float4 p4 = *(const float4*)&pwt[r * 68 + ty * 4];
        ulonglong2 e0 = *(const ulonglong2*)&evs[r * HD + tx * 4];
        ulonglong2 e1 = *(const ulonglong2*)&evs[r * HD + 32 + tx * 4];
        u64 ev[4] = {e0.x, e0.y, e1.x, e1.y};
        u64 pd[4] = {dup2(p4.x), dup2(p4.y), dup2(p4.z), dup2(p4.w)};
#pragma unroll
        for (int i = 0; i < 4; i++)
#pragma unroll
            for (int j = 0; j < 4; j++) fma2(rel2[i][j], pd[i], ev[j]);
    }

#pragma unroll
    for (int i = 0; i < 4; i++) {
        int qg = q0 + ty * 4 + i;
        float inv = 1.0f / l_i[i];
        float emf = __expf(-m_i[i]);       // undo absolute scale on pw
        float* op = &out[((size_t)(b * NS + qg)) * ND + h * HD];
        float o[8];
#pragma unroll
        for (int j = 0; j < 4; j++) {
            float2 a = unpack2(acc2[i][j]);
            float2 rl = unpack2(rel2[i][j]);
            o[j * 2 + 0] = (a.x + rl.x * emf) * inv;
            o[j * 2 + 1] = (a.y + rl.y * emf) * inv;
        }
        *(float4*)&op[tx * 4]      = make_float4(o[0], o[1], o[2], o[3]);
        *(float4*)&op[32 + tx * 4] = make_float4(o[4], o[5], o[6], o[7]);
    }
}

// ---------------------------------------------------------------------------
extern "C" void kernel_launch(void* const* d_in, const int* in_sizes, int n_in,
                              void* d_out, int out_size)
{
    const float* hid   = (const float*)d_in[0];
    const float* mask  = (const float*)d_in[1];
    const float* Wq    = (const float*)d_in[2];
    const float* bq    = (const float*)d_in[3];
    const float* Wk    = (const float*)d_in[4];
    const float* bk    = (const float*)d_in[5];
    const float* Wv    = (const float*)d_in[6];
    const float* bv    = (const float*)d_in[7];
    const float* emb_k = (const float*)d_in[8];
    const float* emb_v = (const float*)d_in[9];
    float* out = (float*)d_out;

    dim3 g1(ND / 128, (NB * NS) / 128, 3);
    qkv_kernel<<<g1, 256>>>(hid, Wq, bq, Wk, bk, Wv, bv);

    qe_kernel<<<(NB * NH * NS) / 32, 128>>>(emb_k);

    size_t smem = (size_t)(6 * 64 * 68 + NR * 68 + 64) * sizeof(float);
    cudaFuncSetAttribute(attn_kernel, cudaFuncAttributeMaxDynamicSharedMemorySize,
                         (int)smem);
    attn_kernel<<<dim3(NS / 64, NB * NH), 128, smem>>>(mask, emb_v, out);
}

// round 13
// speedup vs baseline: 1.1343x; 1.0705x over previous
#include <cuda_runtime.h>
#include <cstdint>

#define NB 2
#define NS 2048
#define ND 1024
#define NH 16
#define HD 64
#define NR 129   // 2*64+1 relative buckets
#define NQT (NS / 64)

typedef unsigned long long u64;

__device__ __forceinline__ void fma2(u64& d, u64 a, u64 b) {
    asm("fma.rn.f32x2 %0, %1, %2, %0;" : "+l"(d) : "l"(a), "l"(b));
}
__device__ __forceinline__ void mul2(u64& d, u64 a) {
    asm("mul.rn.f32x2 %0, %0, %1;" : "+l"(d) : "l"(a));
}
__device__ __forceinline__ u64 dup2(float x) {
    u64 o; unsigned r = __float_as_uint(x);
    asm("mov.b64 %0, {%1, %1};" : "=l"(o) : "r"(r));
    return o;
}
__device__ __forceinline__ float2 unpack2(u64 v) {
    unsigned lo, hi;
    asm("mov.b64 {%0, %1}, %2;" : "=r"(lo), "=r"(hi) : "l"(v));
    return make_float2(__uint_as_float(lo), __uint_as_float(hi));
}
__device__ __forceinline__ void cpa16(uint32_t s, const void* g) {
    asm volatile("cp.async.cg.shared.global [%0], [%1], 16;" :: "r"(s), "l"(g));
}
__device__ __forceinline__ void cp_commit() {
    asm volatile("cp.async.commit_group;");
}
__device__ __forceinline__ void cp_wait0() {
    asm volatile("cp.async.wait_group 0;");
}
__device__ __forceinline__ uint32_t smem_u32(const void* p) {
    return (uint32_t)__cvta_generic_to_shared(p);
}

// scratch (allocation-free rule: device globals)
__device__ float g_q[(size_t)NB * NH * NS * HD];   // pre-scaled by 1/sqrt(d)
__device__ float g_k[(size_t)NB * NH * NS * HD];
__device__ float g_v[(size_t)NB * NH * NS * HD];
__device__ float g_qe[(size_t)NB * NH * NS * NR];  // q . emb_k[r], scale folded in
__device__ float g_pw[(size_t)NB * NH * NQT * NR * 64];  // per-CTA bucket probs [r][q]

// ---------------------------------------------------------------------------
// Kernel 1: fused QKV projection. 128x128 tile, BK=16, double-buffered smem,
// one barrier per step, B staged via cp.async (2 chunks/thread), FFMA2.
// ---------------------------------------------------------------------------
#define QBK 16
__global__ __launch_bounds__(256) void qkv_kernel(
    const float* __restrict__ hid,
    const float* __restrict__ Wq, const float* __restrict__ bq,
    const float* __restrict__ Wk, const float* __restrict__ bk,
    const float* __restrict__ Wv, const float* __restrict__ bv)
{
    const int bz = blockIdx.z;
    const float* W    = (bz == 0) ? Wq : (bz == 1) ? Wk : Wv;
    const float* bias = (bz == 0) ? bq : (bz == 1) ? bk : bv;
    float* out        = (bz == 0) ? g_q : (bz == 1) ? g_k : g_v;
    const float sc    = (bz == 0) ? 0.125f : 1.0f;   // 1/sqrt(64)

    __shared__ __align__(16) float As[2][QBK][132];   // [k][m]
    __shared__ __align__(16) float Bs[2][QBK][132];   // [k][n]

    const int tid = threadIdx.x;
    const int tx = tid & 15, ty = tid >> 4;
    const int m0 = blockIdx.y * 128, n0 = blockIdx.x * 128;

    const int arow = tid >> 1;            // 0..127 (m)
    const int acol = (tid & 1) * 8;       // k offset 0 or 8
    const int brow = tid >> 4;            // 0..15 (k)
    const int bc8  = (tid & 15) * 8;      // n offset, 8 floats via 2 cpa16

    u64 acc2[8][4];
#pragma unroll
    for (int i = 0; i < 8; i++)
#pragma unroll
        for (int j = 0; j < 4; j++) acc2[i][j] = 0ULL;

    // ---- prologue: stage tile 0 into buffer 0 ----
    {
        float4 a0 = *(const float4*)&hid[(size_t)(m0 + arow) * ND + acol];
        float4 a1 = *(const float4*)&hid[(size_t)(m0 + arow) * ND + acol + 4];
        As[0][acol + 0][arow] = a0.x; As[0][acol + 1][arow] = a0.y;
        As[0][acol + 2][arow] = a0.z; As[0][acol + 3][arow] = a0.w;
        As[0][acol + 4][arow] = a1.x; As[0][acol + 5][arow] = a1.y;
        As[0][acol + 6][arow] = a1.z; As[0][acol + 7][arow] = a1.w;
        cpa16(smem_u32(&Bs[0][brow][bc8]),     &W[(size_t)brow * ND + n0 + bc8]);
        cpa16(smem_u32(&Bs[0][brow][bc8 + 4]), &W[(size_t)brow * ND + n0 + bc8 + 4]);
        cp_commit();
        cp_wait0();
    }
    __syncthreads();

    int buf = 0;
    for (int k0 = 0; k0 < ND; k0 += QBK) {
        const bool more = (k0 + QBK) < ND;
        float4 a_n0, a_n1;
        if (more) {
            a_n0 = *(const float4*)&hid[(size_t)(m0 + arow) * ND + k0 + QBK + acol];
            a_n1 = *(const float4*)&hid[(size_t)(m0 + arow) * ND + k0 + QBK + acol + 4];
            cpa16(smem_u32(&Bs[buf ^ 1][brow][bc8]),
                  &W[(size_t)(k0 + QBK + brow) * ND + n0 + bc8]);
            cpa16(smem_u32(&Bs[buf ^ 1][brow][bc8 + 4]),
                  &W[(size_t)(k0 + QBK + brow) * ND + n0 + bc8 + 4]);
            cp_commit();
        }
#pragma unroll
        for (int kk = 0; kk < QBK; kk++) {
            float4 a0 = *(const float4*)&As[buf][kk][ty * 8];
            float4 a1 = *(const float4*)&As[buf][kk][ty * 8 + 4];
            ulonglong2 bl0 = *(const ulonglong2*)&Bs[buf][kk][tx * 8];
            ulonglong2 bl1 = *(const ulonglong2*)&Bs[buf][kk][tx * 8 + 4];
            u64 bvp[4] = {bl0.x, bl0.y, bl1.x, bl1.y};
            float av[8] = {a0.x, a0.y, a0.z, a0.w, a1.x, a1.y, a1.z, a1.w};
#pragma unroll
            for (int i = 0; i < 8; i++) {
                u64 ad = dup2(av[i]);
#pragma unroll
                for (int j = 0; j < 4; j++) fma2(acc2[i][j], ad, bvp[j]);
            }
        }
        if (more) {
            int nb = buf ^ 1;
            As[nb][acol + 0][arow] = a_n0.x; As[nb][acol + 1][arow] = a_n0.y;
            As[nb][acol + 2][arow] = a_n0.z; As[nb][acol + 3][arow] = a_n0.w;
            As[nb][acol + 4][arow] = a_n1.x; As[nb][acol + 5][arow] = a_n1.y;
            As[nb][acol + 6][arow] = a_n1.z; As[nb][acol + 7][arow] = a_n1.w;
            cp_wait0();
        }
        __syncthreads();
        buf ^= 1;
    }

#pragma unroll
    for (int i = 0; i < 8; i++) {
        int m = m0 + ty * 8 + i;           // m = b*S + s
        int b = m >> 11, s = m & (NS - 1);
#pragma unroll
        for (int jj = 0; jj < 2; jj++) {
            int n = n0 + tx * 8 + jj * 4;  // n = h*64 + d
            int h = n >> 6, dd = n & 63;
            float2 p0 = unpack2(acc2[i][jj * 2 + 0]);
            float2 p1 = unpack2(acc2[i][jj * 2 + 1]);
            float4 o;
            o.x = (p0.x + bias[n + 0]) * sc;
            o.y = (p0.y + bias[n + 1]) * sc;
            o.z = (p1.x + bias[n + 2]) * sc;
            o.w = (p1.y + bias[n + 3]) * sc;
            *(float4*)&out[(((size_t)(b * NH + h) * NS) + s) * HD + dd] = o;
        }
    }
}

// ---------------------------------------------------------------------------
// Kernel 2: qe[g][r] = sum_d g_q[g][d] * emb_k[r][d]
// ---------------------------------------------------------------------------
__global__ __launch_bounds__(128) void qe_kernel(const float* __restrict__ emb_k)
{
    __shared__ float eks[NR * 65];
    __shared__ float qs[32 * 65];
    const int tid = threadIdx.x;
    const size_t g0 = (size_t)blockIdx.x * 32;

    for (int i = tid; i < NR * HD; i += 128) {
        int r = i >> 6, d = i & 63;
        eks[r * 65 + d] = emb_k[i];
    }
    for (int i = tid; i < 32 * HD; i += 128) {
        int ql = i >> 6, d = i & 63;
        qs[ql * 65 + d] = g_q[(g0 + ql) * HD + d];
    }
    __syncthreads();

    for (int i = tid; i < 32 * NR; i += 128) {
        int ql = i / NR, r = i - ql * NR;
        float s = 0.f;
#pragma unroll
        for (int d = 0; d < HD; d++) s += qs[ql * 65 + d] * eks[r * 65 + d];
        g_qe[(g0 + ql) * NR + r] = s;
    }
}

// ---------------------------------------------------------------------------
// Kernel 3: flash attention. 128 threads, 4q x 8d microtile (R10 shape),
// pw bucket table in GLOBAL scratch (per-CTA slice) -> smem 68KB, 3 CTAs/SM.
// FFMA2 packed, pw in absolute exp units.
// ---------------------------------------------------------------------------
__global__ __launch_bounds__(128) void attn_kernel(
    const float* __restrict__ mask, const float* __restrict__ emb_v,
    float* __restrict__ out)
{
    extern __shared__ float sm[];
    float* Qs = sm;                      // [64][68]
    float* Ks = Qs + 64 * 68;            // [64][68]
    float* Vs = Ks + 64 * 68;            // [64][68]
    float* Pt = Vs + 64 * 68;            // [key][q]
    float* mk = Pt + 64 * 68;            // [64]

    const int tid = threadIdx.x;
    const int tx = tid & 7, ty = tid >> 3;          // ty in [0,16)
    const int qt = blockIdx.x, bh = blockIdx.y;
    const int b = bh >> 4, h = bh & 15;
    const size_t base = (size_t)bh * NS * HD;
    const int q0 = qt * 64;

    float* pwg = g_pw + ((size_t)(bh * NQT + qt)) * (NR * 64);  // [r][q] stride 64

    const int srow = tid >> 4;            // 0..7, staging rows
    const int sc4  = (tid & 15) * 4;      // 16B chunk

    // stage Q tile (cp.async) + zero pw slice (global, float4)
    for (int r8 = 0; r8 < 64; r8 += 8)
        cpa16(smem_u32(&Qs[(r8 + srow) * 68 + sc4]),
              &g_q[base + (size_t)(q0 + r8 + srow) * HD + sc4]);
    cp_commit();
    {
        float4 z4 = make_float4(0.f, 0.f, 0.f, 0.f);
        for (int i = tid; i < NR * 16; i += 128)
            ((float4*)pwg)[i] = z4;
    }

    float qe0[4], qe128[4];
    const size_t qeb = ((size_t)bh * NS + q0) * NR;
#pragma unroll
    for (int i = 0; i < 4; i++) {
        int q = ty * 4 + i;
        qe0[i]   = g_qe[qeb + (size_t)q * NR + 0];
        qe128[i] = g_qe[qeb + (size_t)q * NR + 128];
    }

    float m_i[4], l_i[4];
    u64 acc2[4][4];
#pragma unroll
    for (int i = 0; i < 4; i++) {
        m_i[i] = -1e30f; l_i[i] = 0.f;
#pragma unroll
        for (int j = 0; j < 4; j++) acc2[i][j] = 0ULL;
    }

    for (int kt = 0; kt < NS / 64; kt++) {
        const int k0 = kt * 64;
        // stage K/V via cp.async (prev-tile barrier protects buffers)
        for (int r8 = 0; r8 < 64; r8 += 8) {
            cpa16(smem_u32(&Ks[(r8 + srow) * 68 + sc4]),
                  &g_k[base + (size_t)(k0 + r8 + srow) * HD + sc4]);
            cpa16(smem_u32(&Vs[(r8 + srow) * 68 + sc4]),
                  &g_v[base + (size_t)(k0 + r8 + srow) * HD + sc4]);
        }
        cp_commit();
        if (tid < 64) mk[tid] = mask[b * NS + k0 + tid];
        cp_wait0();
        __syncthreads();

        // ---- S = Q K^T  (FFMA2 packed along d) ----
        u64 s2[4][8];
#pragma unroll
        for (int i = 0; i < 4; i++)
#pragma unroll
            for (int j = 0; j < 8; j++) s2[i][j] = 0ULL;
#pragma unroll 4
        for (int c4 = 0; c4 < HD; c4 += 4) {
            ulonglong2 aq[4], bk[8];
#pragma unroll
            for (int i = 0; i < 4; i++)
                aq[i] = *(const ulonglong2*)&Qs[(ty * 4 + i) * 68 + c4];
#pragma unroll
            for (int j = 0; j < 8; j++)
                bk[j] = *(const ulonglong2*)&Ks[(tx + 8 * j) * 68 + c4];
#pragma unroll
            for (int i = 0; i < 4; i++)
#pragma unroll
                for (int j = 0; j < 8; j++) {
                    fma2(s2[i][j], aq[i].x, bk[j].x);
                    fma2(s2[i][j], aq[i].y, bk[j].y);
                }
        }
        float s[4][8];
#pragma unroll
        for (int i = 0; i < 4; i++)
#pragma unroll
            for (int j = 0; j < 8; j++) {
                float2 p = unpack2(s2[i][j]);
                s[i][j] = p.x + p.y;
            }

        // ---- relative bias + mask ----
        const int dt = qt - kt;
        if (dt >= 2) {
#pragma unroll
            for (int i = 0; i < 4; i++)
#pragma unroll
                for (int j = 0; j < 8; j++) s[i][j] += qe128[i] + mk[tx + 8 * j];
        } else if (dt <= -2) {
#pragma unroll
            for (int i = 0; i < 4; i++)
#pragma unroll
                for (int j = 0; j < 8; j++) s[i][j] += qe0[i] + mk[tx + 8 * j];
        } else {
#pragma unroll
            for (int i = 0; i < 4; i++) {
                int qg = q0 + ty * 4 + i;
                const float* qer = &g_qe[((size_t)bh * NS + qg) * NR];
#pragma unroll
                for (int j = 0; j < 8; j++) {
                    int kg = k0 + tx + 8 * j;
                    int rp = qg - kg;
                    rp = rp < -64 ? -64 : (rp > 64 ? 64 : rp);
                    s[i][j] += __ldg(&qer[rp + 64]) + mk[tx + 8 * j];
                }
            }
        }

        // ---- streaming softmax ----
        float c[4], rstile[4], em[4];
#pragma unroll
        for (int i = 0; i < 4; i++) {
            float rmax = s[i][0];
#pragma unroll
            for (int j = 1; j < 8; j++) rmax = fmaxf(rmax, s[i][j]);
#pragma unroll
            for (int o = 1; o < 8; o <<= 1)
                rmax = fmaxf(rmax, __shfl_xor_sync(0xffffffffu, rmax, o));
            float mn = fmaxf(m_i[i], rmax);
            c[i] = __expf(m_i[i] - mn);
            m_i[i] = mn;
            em[i] = __expf(mn);            // abs-scale for pw (scores bounded)
            float rs = 0.f;
#pragma unroll
            for (int j = 0; j < 8; j++) { s[i][j] = __expf(s[i][j] - mn); rs += s[i][j]; }
#pragma unroll
            for (int o = 1; o < 8; o <<= 1) rs += __shfl_xor_sync(0xffffffffu, rs, o);
            l_i[i] = l_i[i] * c[i] + rs;
            rstile[i] = rs;
            u64 cd = dup2(c[i]);
#pragma unroll
            for (int j = 0; j < 4; j++) mul2(acc2[i][j], cd);
        }

        // stage P transposed [key][q]
#pragma unroll
        for (int i = 0; i < 4; i++)
#pragma unroll
            for (int j = 0; j < 8; j++)
                Pt[(tx + 8 * j) * 68 + ty * 4 + i] = s[i][j];

        // ---- bucket-probability accumulation (ABSOLUTE exp units, global) ----
        // writer-unique addresses within a tile; cross-tile visibility via
        // write-through L1 + per-tile __syncthreads.
        if (dt >= 2) {
            if (tx == 0)
#pragma unroll
                for (int i = 0; i < 4; i++)
                    pwg[128 * 64 + ty * 4 + i] += rstile[i] * em[i];
        } else if (dt <= -2) {
            if (tx == 0)
#pragma unroll
                for (int i = 0; i < 4; i++)
                    pwg[0 * 64 + ty * 4 + i] += rstile[i] * em[i];
        } else if (dt == -1) {
#pragma unroll
            for (int i = 0; i < 4; i++) {
                int qg = q0 + ty * 4 + i;
                float csum = 0.f;
#pragma unroll
                for (int j = 0; j < 8; j++) {
                    int kg = k0 + tx + 8 * j;
                    int rp = qg - kg;
                    float ps = s[i][j] * em[i];
                    if (rp <= -64) csum += ps;
                    else pwg[(rp + 64) * 64 + ty * 4 + i] += ps;
                }
#pragma unroll
                for (int o = 1; o < 8; o <<= 1)
                    csum += __shfl_xor_sync(0xffffffffu, csum, o);
                if (tx == 0) pwg[0 * 64 + ty * 4 + i] += csum;
            }
        } else if (dt == 1) {
#pragma unroll
            for (int i = 0; i < 4; i++) {
                int qg = q0 + ty * 4 + i;
                float csum = 0.f;
#pragma unroll
                for (int j = 0; j < 8; j++) {
                    int kg = k0 + tx + 8 * j;
                    int rp = qg - kg;
                    float ps = s[i][j] * em[i];
                    if (rp >= 64) csum += ps;
                    else pwg[(rp + 64) * 64 + ty * 4 + i] += ps;
                }
#pragma unroll
                for (int o = 1; o < 8; o <<= 1)
                    csum += __shfl_xor_sync(0xffffffffu, csum, o);
                if (tx == 0) pwg[128 * 64 + ty * 4 + i] += csum;
            }
        } else {
#pragma unroll
            for (int i = 0; i < 4; i++) {
                int qg = q0 + ty * 4 + i;
#pragma unroll
                for (int j = 0; j < 8; j++) {
                    int kg = k0 + tx + 8 * j;
                    int rp = qg - kg;
                    pwg[(rp + 64) * 64 + ty * 4 + i] += s[i][j] * em[i];
                }
            }
        }
        __syncthreads();   // Pt visible to all before PV; orders pw RMW

        // ---- O += P V  (d-cols tx*4 and 32+tx*4: conflict-free) ----
#pragma unroll 4
        for (int k = 0; k < 64; k++) {
            float4 p4 = *(const float4*)&Pt[k * 68 + ty * 4];
            ulonglong2 v0 = *(const ulonglong2*)&Vs[k * 68 + tx * 4];
            ulonglong2 v1 = *(const ulonglong2*)&Vs[k * 68 + 32 + tx * 4];
            u64 vv[4] = {v0.x, v0.y, v1.x, v1.y};
            u64 pd[4] = {dup2(p4.x), dup2(p4.y), dup2(p4.z), dup2(p4.w)};
#pragma unroll
            for (int i = 0; i < 4; i++)
#pragma unroll
                for (int j = 0; j < 4; j++) fma2(acc2[i][j], pd[i], vv[j]);
        }
        __syncthreads();   // before next tile overwrites Ks/Vs
    }

    // ---- epilogue: ctx_rel = pw @ emb_v ----
    float* evs = Qs;   // 129*64 = 8256 floats <= 8704 (Qs+Ks)
    for (int i = tid; i < NR * HD; i += 128) evs[i] = emb_v[i];
    __syncthreads();   // also orders all pw global writes before reads below

    u64 rel2[4][4];
#pragma unroll
    for (int i = 0; i < 4; i++)
#pragma unroll
        for (int j = 0; j < 4; j++) rel2[i][j] = 0ULL;
#pragma unroll 4
    for (int r = 0; r < NR; r++) {
        float4 p4 = *(const float4*)&pwg[r * 64 + ty * 4];
        ulonglong2 e0 = *(const ulonglong2*)&evs[r * HD + tx * 4];
        ulonglong2 e1 = *(const ulonglong2*)&evs[r * HD + 32 + tx * 4];
        u64 ev[4] = {e0.x, e0.y, e1.x, e1.y};
        u64 pd[4] = {dup2(p4.x), dup2(p4.y), dup2(p4.z), dup2(p4.w)};
#pragma unroll
        for (int i = 0; i < 4; i++)
#pragma unroll
            for (int j = 0; j < 4; j++) fma2(rel2[i][j], pd[i], ev[j]);
    }

#pragma unroll
    for (int i = 0; i < 4; i++) {
        int qg = q0 + ty * 4 + i;
        float inv = 1.0f / l_i[i];
        float emf = __expf(-m_i[i]);       // undo absolute scale on pw
        float* op = &out[((size_t)(b * NS + qg)) * ND + h * HD];
        float o[8];
#pragma unroll
        for (int j = 0; j < 4; j++) {
            float2 a = unpack2(acc2[i][j]);
            float2 rl = unpack2(rel2[i][j]);
            o[j * 2 + 0] = (a.x + rl.x * emf) * inv;
            o[j * 2 + 1] = (a.y + rl.y * emf) * inv;
        }
        *(float4*)&op[tx * 4]      = make_float4(o[0], o[1], o[2], o[3]);
        *(float4*)&op[32 + tx * 4] = make_float4(o[4], o[5], o[6], o[7]);
    }
}

// ---------------------------------------------------------------------------
extern "C" void kernel_launch(void* const* d_in, const int* in_sizes, int n_in,
                              void* d_out, int out_size)
{
    const float* hid   = (const float*)d_in[0];
    const float* mask  = (const float*)d_in[1];
    const float* Wq    = (const float*)d_in[2];
    const float* bq    = (const float*)d_in[3];
    const float* Wk    = (const float*)d_in[4];
    const float* bk    = (const float*)d_in[5];
    const float* Wv    = (const float*)d_in[6];
    const float* bv    = (const float*)d_in[7];
    const float* emb_k = (const float*)d_in[8];
    const float* emb_v = (const float*)d_in[9];
    float* out = (float*)d_out;

    dim3 g1(ND / 128, (NB * NS) / 128, 3);
    qkv_kernel<<<g1, 256>>>(hid, Wq, bq, Wk, bk, Wv, bv);

    qe_kernel<<<(NB * NH * NS) / 32, 128>>>(emb_k);

    size_t smem = (size_t)(4 * 64 * 68 + 64) * sizeof(float);
    cudaFuncSetAttribute(attn_kernel, cudaFuncAttributeMaxDynamicSharedMemorySize,
                         (int)smem);
    attn_kernel<<<dim3(NS / 64, NB * NH), 128, smem>>>(mask, emb_v, out);
}